// round 9
// baseline (speedup 1.0000x reference)
#include <cuda_runtime.h>
#include <math.h>
#include <cstdint>

#define BSZ  16      // batch
#define NCAP 1152    // primary caps
#define DP   8       // dim primary
#define DDIG 10      // digit caps
#define DD   16      // dim digit

#define TILE_N 16
#define NT (NCAP / TILE_N)   // 72

#define NCH 36               // n-chunks per batch in k2
#define CHN (NCAP / NCH)     // 32

// Scratch (device globals; zero-init at load; invariants restored every call)
__device__ float g_U [BSZ * DDIG * NCAP * DD];   // U_hat [b][d][n][j]
__device__ float g_T [BSZ * DDIG * DD];          // T (k1 atomics; re-zeroed by k2)
__device__ float g_S [BSZ * DDIG * DD];          // S accumulator (k2 atomics; re-zeroed)
__device__ unsigned int g_cnt[BSZ];              // self-resetting wrap counter

// -------------------------------------------------------------------------
// K1: votes U_hat[b,d,n,j] = W[d,n,j,:]·u[b,n,:]  +  atomic T accumulation
// Grid (DDIG, NT) = 720 CTAs x 256 threads.   (proven R7/R8)
// -------------------------------------------------------------------------
__global__ __launch_bounds__(256) void k1_votes(
    const float* __restrict__ u,   // [B][N][DP]
    const float* __restrict__ W)   // [D][N][DD][DP]
{
    const int d    = blockIdx.x;
    const int tile = blockIdx.y;
    const int n0   = tile * TILE_N;
    const int t    = threadIdx.x;
    const int j    = t & 15;
    const int nl   = t >> 4;
    const int n    = n0 + nl;
    const int lane = t & 31;
    const int w    = t >> 5;

    const float4* wp = reinterpret_cast<const float4*>(
        W + ((size_t)(d * NCAP + n) * DD + j) * DP);
    const float4 w0 = wp[0];
    const float4 w1 = wp[1];

    __shared__ __align__(16) float us[BSZ][TILE_N][DP];   // 8 KB
    __shared__ float red[BSZ][8][DD];                     // 8 KB

    #pragma unroll
    for (int it = 0; it < 2; ++it) {
        const int idx = it * 256 + t;
        const int b   = idx >> 5;
        const int rem = idx & 31;
        const float4 v = reinterpret_cast<const float4*>(
            u + (size_t)b * NCAP * DP + (size_t)n0 * DP)[rem];
        reinterpret_cast<float4*>(&us[b][0][0])[rem] = v;
    }
    __syncthreads();

    #pragma unroll
    for (int b = 0; b < BSZ; ++b) {
        const float4* up = reinterpret_cast<const float4*>(&us[b][nl][0]);
        const float4 u0 = up[0];
        const float4 u1 = up[1];
        const float acc = w0.x * u0.x + w0.y * u0.y + w0.z * u0.z + w0.w * u0.w
                        + w1.x * u1.x + w1.y * u1.y + w1.z * u1.z + w1.w * u1.w;
        g_U[((size_t)(b * DDIG + d) * NCAP + n) * DD + j] = acc;

        const float ps = acc + __shfl_xor_sync(0xffffffffu, acc, 16);
        if (lane < 16) red[b][w][lane] = ps;
    }
    __syncthreads();

    {
        const int b2 = t >> 4;
        const int j2 = t & 15;
        float s = 0.f;
        #pragma unroll
        for (int ww = 0; ww < 8; ++ww) s += red[b2][ww][j2];
        atomicAdd(&g_T[(b2 * DDIG + d) * DD + j2], s);
    }
}

// -------------------------------------------------------------------------
// K2: SMEM-tiled, occupancy-tuned: CHN=32, grid 576, 4 CTAs/SM (32 warps).
// Load U tile once (T-dots in flight), softmax, combine from SMEM,
// atomic partial S into g_S, last-CTA-per-b finalize + squash.
// -------------------------------------------------------------------------
__global__ __launch_bounds__(256, 4) void k2_rest(
    const float* __restrict__ Bp,   // [D][1][N]
    float* __restrict__ out)        // [B][D][DD]
{
    const int b     = blockIdx.x;
    const int chunk = blockIdx.y;
    const int t     = threadIdx.x;
    const int nbase = chunk * CHN;

    __shared__ float Tsm[DDIG][DD];                       // 640 B
    __shared__ __align__(16) float Us[DDIG][CHN][DD];     // 20 KB
    __shared__ float a_s[CHN][12];                        // 1.5 KB (pad)
    __shared__ float wgt_s[DDIG][CHN];                    // 1.25 KB
    __shared__ float Ssm[DDIG][DD];
    __shared__ float coef[DDIG];
    __shared__ unsigned int is_last;

    if (t < DDIG * DD) Tsm[t >> 4][t & 15] = g_T[b * DDIG * DD + t];
    __syncthreads();

    const float inv_sqrt8 = 0.3535533905932738f;

    // ---- load phase: 320 rows (d*32+nl); 1-2 rows/thread, loads up front ----
    {
        auto rowp = [&](int r) {
            const int d  = r >> 5;          // CHN == 32
            const int nl = r & 31;
            return reinterpret_cast<const float4*>(
                g_U + ((size_t)(b * DDIG + d) * NCAP + nbase + nl) * DD);
        };
        auto proc = [&](int r, const float4* A) {
            const int d  = r >> 5;
            const int nl = r & 31;
            float4* s = reinterpret_cast<float4*>(&Us[d][nl][0]);
            s[0] = A[0]; s[1] = A[1]; s[2] = A[2]; s[3] = A[3];
            const float* T = Tsm[d];
            a_s[nl][d] =
                (T[0]  * A[0].x + T[1]  * A[0].y + T[2]  * A[0].z + T[3]  * A[0].w
               + T[4]  * A[1].x + T[5]  * A[1].y + T[6]  * A[1].z + T[7]  * A[1].w
               + T[8]  * A[2].x + T[9]  * A[2].y + T[10] * A[2].z + T[11] * A[2].w
               + T[12] * A[3].x + T[13] * A[3].y + T[14] * A[3].z + T[15] * A[3].w)
               * inv_sqrt8;
        };

        const int r0 = t;
        const int r1 = 256 + t;
        const bool has1 = (r1 < DDIG * CHN);   // t < 64
        float4 A0[4], A1[4];
        const float4* p0 = rowp(r0);
        #pragma unroll
        for (int i = 0; i < 4; ++i) A0[i] = p0[i];
        if (has1) {
            const float4* p1 = rowp(r1);
            #pragma unroll
            for (int i = 0; i < 4; ++i) A1[i] = p1[i];
        }
        proc(r0, A0);
        if (has1) proc(r1, A1);
    }
    __syncthreads();

    // ---- softmax over d (one thread per n) ----
    if (t < CHN) {
        const int nl = t;
        const int n  = nbase + nl;
        float a[DDIG];
        #pragma unroll
        for (int d = 0; d < DDIG; ++d) a[d] = a_s[nl][d];
        float m = a[0];
        #pragma unroll
        for (int d = 1; d < DDIG; ++d) m = fmaxf(m, a[d]);
        float e[DDIG], denom = 0.f;
        #pragma unroll
        for (int d = 0; d < DDIG; ++d) { e[d] = __expf(a[d] - m); denom += e[d]; }
        const float rden = 1.f / denom;
        #pragma unroll
        for (int d = 0; d < DDIG; ++d)
            wgt_s[d][nl] = e[d] * rden + __ldg(&Bp[(size_t)d * NCAP + n]);
    }
    __syncthreads();

    // ---- combine from SMEM: threads (16 j x 16 sub); d innermost ----
    {
        const int j    = t & 15;
        const int sub  = t >> 4;
        const int lane = t & 31;

        float acc[DDIG];
        #pragma unroll
        for (int d = 0; d < DDIG; ++d) acc[d] = 0.f;

        #pragma unroll
        for (int k = 0; k < CHN / 16; ++k) {     // 2 iters
            const int nl = k * 16 + sub;
            #pragma unroll
            for (int d = 0; d < DDIG; ++d)
                acc[d] += wgt_s[d][nl] * Us[d][nl][j];
        }

        #pragma unroll
        for (int d = 0; d < DDIG; ++d)
            acc[d] += __shfl_xor_sync(0xffffffffu, acc[d], 16);

        if (lane < 16) {     // lane == j here
            #pragma unroll
            for (int d = 0; d < DDIG; ++d)
                atomicAdd(&g_S[(b * DDIG + d) * DD + lane], acc[d]);
        }
    }

    // ---- last-CTA-per-b finalize ----
    __threadfence();
    __syncthreads();
    if (t == 0)
        is_last = (atomicInc(&g_cnt[b], NCH - 1) == NCH - 1) ? 1u : 0u;
    __syncthreads();
    if (!is_last) return;

    if (t < DDIG * DD) {
        const float sv = __ldcg(&g_S[b * DDIG * DD + t]);   // L2-fresh
        Ssm[t >> 4][t & 15] = sv;
        g_S[b * DDIG * DD + t] = 0.f;    // restore invariant for next call
        g_T[b * DDIG * DD + t] = 0.f;
    }
    __syncthreads();
    if (t < DDIG) {
        float nn = 0.f;
        #pragma unroll
        for (int jj = 0; jj < DD; ++jj) nn += Ssm[t][jj] * Ssm[t][jj];
        const float norm = sqrtf(nn);
        const float EPS  = 1e-7f;
        coef[t] = (1.f - 1.f / (__expf(norm) + EPS)) / (norm + EPS);
    }
    __syncthreads();
    if (t < DDIG * DD)
        out[(size_t)b * DDIG * DD + t] = coef[t >> 4] * Ssm[t >> 4][t & 15];
}

// -------------------------------------------------------------------------
extern "C" void kernel_launch(void* const* d_in, const int* in_sizes, int n_in,
                              void* d_out, int out_size)
{
    const float* u  = (const float*)d_in[0];   // primary_caps [16,1152,8]
    const float* W  = (const float*)d_in[1];   // W            [10,1152,16,8]
    const float* Bp = (const float*)d_in[2];   // B_prior      [10,1,1152]
    float* out      = (float*)d_out;           // [16,10,16]

    (void)in_sizes; (void)n_in; (void)out_size;

    k1_votes<<<dim3(DDIG, NT), 256>>>(u, W);
    k2_rest <<<dim3(BSZ, NCH), 256>>>(Bp, out);
}